// round 10
// baseline (speedup 1.0000x reference)
#include <cuda_runtime.h>

#define Tn 512
#define Bn 2
#define Hn 128
#define En 32
#define Vn 32000

// ---------------- scratch (no allocations allowed) ----------------
__device__ float g_xp[Bn * Tn * Hn];    // input projections + biases
__device__ float g_rnn[Bn * Tn * Hn];   // RNN outputs
__device__ float g_q[Bn * Tn * Hn];     // query = rnn @ W1^T
__device__ float g_k[Bn * Tn * Hn];     // keys  = rnn @ W2^T
__device__ float g_proj[Bn * Tn * Hn];  // relu([rnn,ctx] @ Wp^T + bp)

// ---------------- f32x2 packed-FMA helpers (SASS FFMA2, PTX-only) ----------------
#define FMA_F32X2(d, a, b, c) \
    asm("fma.rn.f32x2 %0, %1, %2, %3;" : "=l"(d) : "l"(a), "l"(b), "l"(c))
#define PACK_DUP_F32X2(d, x) \
    asm("mov.b64 %0, {%1, %1};" : "=l"(d) : "f"(x))
__device__ __forceinline__ float f2sum(unsigned long long p) {
    float lo, hi;
    asm("mov.b64 {%0, %1}, %2;" : "=f"(lo), "=f"(hi) : "l"(p));
    return lo + hi;
}

// accurate MUFU tanh (~1e-6 rel err): rare-fallback path only
__device__ __forceinline__ float fast_tanh(float x) {
    x = fminf(fmaxf(x, -15.f), 15.f);
    float e = __expf(2.f * x);
    return __fdividef(e - 1.f, e + 1.f);
}

// Taylor tanh on FMA pipe: abs err <= 1.2e-5 for |x| <= 0.55
#define TANH_C1 (-0.33333333f)
#define TANH_C2 (0.13333334f)
#define TANH_C3 (-0.05396825f)
#define TANH_C4 (0.02186949f)
__device__ __forceinline__ float poly_tanh(float x) {
    float u = x * x;
    float p = fmaf(u, TANH_C4, TANH_C3);
    p = fmaf(u, p, TANH_C2);
    p = fmaf(u, p, TANH_C1);
    p = fmaf(u, p, 1.0f);
    return x * p;
}

// ---------------- K1: embedding + input projection (detect folded in) ----------------
__global__ void k_embed(const unsigned* __restrict__ xw,
                        const float* __restrict__ etab,
                        const float* __restrict__ W_ih,
                        const float* __restrict__ b_ih,
                        const float* __restrict__ b_hh) {
    int bt = blockIdx.x;
    int h = threadIdx.x;
    int nz = 0;
    for (int i = threadIdx.x; i < 512; i += 128)
        nz |= (xw[2 * i + 1] != 0u);
    int is32 = __syncthreads_or(nz);

    __shared__ float emb[En];
    __shared__ int sidx;
    if (threadIdx.x == 0) {
        long long idx;
        if (is32) idx = (long long)(((const int*)xw)[bt]);
        else      idx = ((const long long*)xw)[bt];
        sidx = (int)idx;
    }
    __syncthreads();
    if (h < En) emb[h] = etab[(long long)sidx * En + h];
    __syncthreads();
    float acc = b_ih[h] + b_hh[h];
#pragma unroll
    for (int e = 0; e < En; e++) acc = fmaf(emb[e], W_ih[h * En + e], acc);
    g_xp[bt * Hn + h] = acc;
}

// ---------------- K2: RNN scan — broadcast LDS + FFMA2 ----------------
__global__ void __launch_bounds__(128, 1) k_rnn(const float* __restrict__ hidden,
                                                const float* __restrict__ W_hh,
                                                float* __restrict__ out_hidden) {
    int b = blockIdx.x;
    int j = threadIdx.x;
    unsigned long long w2[64];
    const unsigned long long* wrow = (const unsigned long long*)(W_hh + j * Hn);
#pragma unroll
    for (int q = 0; q < 64; q++) w2[q] = wrow[q];

    __shared__ __align__(16) float hbuf[2][Hn];
    hbuf[0][j] = hidden[b * Hn + j];
    __syncthreads();

    const float* xp = g_xp + b * Tn * Hn;
    float* rnn = g_rnn + b * Tn * Hn;
    float xv_next = xp[j];
    for (int t = 0; t < Tn; t++) {
        float xv = xv_next;
        if (t + 1 < Tn) xv_next = xp[(t + 1) * Hn + j];
        const ulonglong2* h2 = (const ulonglong2*)hbuf[t & 1];
        unsigned long long a0 = 0ull, a1 = 0ull, a2 = 0ull, a3 = 0ull;
#pragma unroll
        for (int q = 0; q < 32; q += 2) {
            ulonglong2 hv0 = h2[q];
            ulonglong2 hv1 = h2[q + 1];
            FMA_F32X2(a0, w2[2 * q + 0], hv0.x, a0);
            FMA_F32X2(a1, w2[2 * q + 1], hv0.y, a1);
            FMA_F32X2(a2, w2[2 * q + 2], hv1.x, a2);
            FMA_F32X2(a3, w2[2 * q + 3], hv1.y, a3);
        }
        float s = (f2sum(a0) + f2sum(a1)) + (f2sum(a2) + f2sum(a3)) + xv;
        float hn = poly_tanh(s);
        if (__any_sync(0xffffffffu, fabsf(s) > 0.55f)) hn = fast_tanh(s);
        hbuf[(t + 1) & 1][j] = hn;
        rnn[t * Hn + j] = hn;
        __syncthreads();
    }
    out_hidden[b * Hn + j] = hbuf[0][j];
}

// ---------------- K3: q/k projections, 32x32 tiles ----------------
__global__ void __launch_bounds__(128) k_qk(const float* __restrict__ W1,
                                            const float* __restrict__ W2) {
    __shared__ float a_s[128][34];
    __shared__ float b_s[128][36];
    int tid = threadIdx.x;
    int tx = tid & 7, ty = tid >> 3;
    int n0 = blockIdx.x * 32, m0 = blockIdx.y * 32;
    const float* W = (n0 < Hn) ? W1 : W2;
    int nb = n0 & (Hn - 1);

    for (int idx = tid; idx < 32 * 128; idx += 128) {
        int r = idx >> 7, k = idx & 127;
        a_s[k][r] = g_rnn[(m0 + r) * Hn + k];
        b_s[k][r] = W[(nb + r) * Hn + k];
    }
    __syncthreads();

    float acc[2][4];
#pragma unroll
    for (int i = 0; i < 2; i++)
#pragma unroll
        for (int jj = 0; jj < 4; jj++) acc[i][jj] = 0.f;
#pragma unroll 4
    for (int k = 0; k < 128; k++) {
        float2 av = *(const float2*)&a_s[k][ty * 2];
        float4 bv = *(const float4*)&b_s[k][tx * 4];
        acc[0][0] = fmaf(av.x, bv.x, acc[0][0]);
        acc[0][1] = fmaf(av.x, bv.y, acc[0][1]);
        acc[0][2] = fmaf(av.x, bv.z, acc[0][2]);
        acc[0][3] = fmaf(av.x, bv.w, acc[0][3]);
        acc[1][0] = fmaf(av.y, bv.x, acc[1][0]);
        acc[1][1] = fmaf(av.y, bv.y, acc[1][1]);
        acc[1][2] = fmaf(av.y, bv.z, acc[1][2]);
        acc[1][3] = fmaf(av.y, bv.w, acc[1][3]);
    }
    float* dst = (n0 < Hn) ? g_q : g_k;
#pragma unroll
    for (int i = 0; i < 2; i++) {
        float4 o = {acc[i][0], acc[i][1], acc[i][2], acc[i][3]};
        *(float4*)&dst[(m0 + ty * 2 + i) * Hn + nb + tx * 4] = o;
    }
}

// ---------------- K4: attention — 4 strided t's per block, warp-per-(t,row-half) ----------------
// Block g (of 128) x batch b handles t in {g, g+128, g+256, g+384}: equal work
// per block, k-tiles shared by 4 t's, ~1150 straight-line instr between barriers.
__global__ void __launch_bounds__(256) k_attn(const float* __restrict__ v,
                                              const float* __restrict__ Wp,
                                              const float* __restrict__ bp,
                                              float* __restrict__ out_w) {
    int g = blockIdx.x;   // 0..127
    int b = blockIdx.y;   // 0..Bn-1
    int tid = threadIdx.x;
    int w = tid >> 5, lane = tid & 31;
    int tq = w & 3;       // which of the 4 t's
    int h4 = w >> 2;      // which 32-row half of the 64-row chunk
    int t_w = g + 128 * tq;
    int t_max = g + 384;

    __shared__ float ks[64][129];     // k / rnn tile, stride-129: conflict-free columns
    __shared__ float q_s[4][Hn];
    __shared__ float v_s[Hn];
    __shared__ float sc[4][Tn];
    __shared__ float ctx_s[4][Hn];
    __shared__ float r_s[4][Hn];

    for (int idx = tid; idx < 4 * Hn; idx += 256) {
        int ti = idx >> 7, h = idx & 127;
        int t = g + 128 * ti;
        q_s[ti][h] = g_q[(b * Tn + t) * Hn + h];
        r_s[ti][h] = g_rnn[(b * Tn + t) * Hn + h];
    }
    if (tid < Hn) v_s[tid] = v[tid];
    __syncthreads();

    // ---- scores: sc[tq][s] = sum_h tanh(q+k)*v, one lane per score ----
    for (int c0 = 0; c0 <= t_max; c0 += 64) {
        for (int idx = tid; idx < 64 * Hn; idx += 256) {
            int r = idx >> 7, h = idx & 127;
            ks[r][h] = g_k[(b * Tn + c0 + r) * Hn + h];
        }
        __syncthreads();
        int s = c0 + h4 * 32 + lane;
        if (s <= t_w) {
            const float* krow = ks[h4 * 32 + lane];
            const float* qrow = q_s[tq];
            float p = 0.f, mabs = 0.f;
#pragma unroll 16
            for (int h = 0; h < Hn; h++) {
                float xv = qrow[h] + krow[h];
                mabs = fmaxf(mabs, fabsf(xv));
                p = fmaf(poly_tanh(xv), v_s[h], p);
            }
            if (mabs > 0.55f) {  // rare accurate fallback
                p = 0.f;
                for (int h = 0; h < Hn; h++)
                    p = fmaf(fast_tanh(qrow[h] + krow[h]), v_s[h], p);
            }
            sc[tq][s] = p;
        }
        __syncthreads();
    }

    // ---- softmax: warp per t, shfl reductions, zero-fill s > t ----
    if (w < 4) {
        int t = g + 128 * w;
        float m = -1e30f;
        for (int s = lane; s <= t; s += 32) m = fmaxf(m, sc[w][s]);
#pragma unroll
        for (int off = 16; off; off >>= 1) m = fmaxf(m, __shfl_xor_sync(0xffffffffu, m, off));
        float ssum = 0.f;
        for (int s = lane; s <= t; s += 32) {
            float e = __expf(sc[w][s] - m);
            sc[w][s] = e;
            ssum += e;
        }
#pragma unroll
        for (int off = 16; off; off >>= 1) ssum += __shfl_xor_sync(0xffffffffu, ssum, off);
        float rinv = __fdividef(1.f, ssum);
        size_t ob = ((size_t)b * Tn + t) * Tn;
        for (int s = lane; s < Tn; s += 32) {
            float wv = (s <= t) ? sc[w][s] * rinv : 0.f;
            sc[w][s] = wv;  // zeros beyond t -> guard-free context
            out_w[ob + s] = wv;
        }
    }
    __syncthreads();

    // ---- context: ctx[tq][h] = sum_s w[s]*rnn[s][h], rnn tiles staged in ks ----
    {
        int h = tid & 127, tg = tid >> 7;  // thread owns (tg, h) and (tg+2, h)
        float ca = 0.f, cb = 0.f;
        for (int c0 = 0; c0 <= t_max; c0 += 64) {
            for (int idx = tid; idx < 64 * Hn; idx += 256) {
                int r = idx >> 7, hh = idx & 127;
                ks[r][hh] = g_rnn[(b * Tn + c0 + r) * Hn + hh];
            }
            __syncthreads();
#pragma unroll 8
            for (int r = 0; r < 64; r++) {
                float kv = ks[r][h];
                ca = fmaf(sc[tg][c0 + r], kv, ca);
                cb = fmaf(sc[tg + 2][c0 + r], kv, cb);
            }
            __syncthreads();
        }
        ctx_s[tg][h] = ca;
        ctx_s[tg + 2][h] = cb;
        __syncthreads();
    }

    // ---- proj: relu([rnn, ctx] @ Wp^T + bp) for the 4 t's ----
    {
        int j = tid >> 1, half = tid & 1;
        const float* wrow = Wp + j * (2 * Hn) + half * Hn;
#pragma unroll
        for (int ti = 0; ti < 4; ti++) {
            const float* src = half ? ctx_s[ti] : r_s[ti];
            float acc = 0.f;
#pragma unroll 16
            for (int k = 0; k < Hn; k++) acc = fmaf(wrow[k], src[k], acc);
            acc += __shfl_xor_sync(0xffffffffu, acc, 1);
            if (half == 0) {
                int t = g + 128 * ti;
                g_proj[(b * Tn + t) * Hn + j] = fmaxf(acc + bp[j], 0.f);
            }
        }
    }
}

// ---------------- K5: logits GEMM with packed f32x2 FMA (R6 form) ----------------
#define BM 64
#define BN 128
#define TK 32
#define LDA 68
#define LDB 132
__global__ void __launch_bounds__(256) k_logits(const float* __restrict__ Wfc,
                                                const float* __restrict__ bfc,
                                                float* __restrict__ logits) {
    __shared__ float a_s[TK][LDA];
    __shared__ float b_s[TK][LDB];
    int tid = threadIdx.x;
    int tx = tid & 15, ty = tid >> 4;
    int m0 = blockIdx.y * BM, n0 = blockIdx.x * BN;
    unsigned long long acc[4][4];
#pragma unroll
    for (int i = 0; i < 4; i++)
#pragma unroll
        for (int jj = 0; jj < 4; jj++) acc[i][jj] = 0ull;

    for (int kc = 0; kc < Hn / TK; kc++) {
        for (int idx = tid; idx < BM * TK; idx += 256) {
            int r = idx >> 5, k = idx & 31;
            a_s[k][r] = g_proj[(m0 + r) * Hn + kc * TK + k];
        }
        for (int idx = tid; idx < BN * TK; idx += 256) {
            int n = idx >> 5, k = idx & 31;
            b_s[k][n] = Wfc[(size_t)(n0 + n) * Hn + kc * TK + k];
        }
        __syncthreads();
#pragma unroll 8
        for (int k = 0; k < TK; k++) {
            float4 av = *(const float4*)&a_s[k][ty * 4];
            ulonglong2 bv0 = *(const ulonglong2*)&b_s[k][tx * 8];
            ulonglong2 bv1 = *(const ulonglong2*)&b_s[k][tx * 8 + 4];
            unsigned long long aa[4];
            PACK_DUP_F32X2(aa[0], av.x);
            PACK_DUP_F32X2(aa[1], av.y);
            PACK_DUP_F32X2(aa[2], av.z);
            PACK_DUP_F32X2(aa[3], av.w);
#pragma unroll
            for (int i = 0; i < 4; i++) {
                FMA_F32X2(acc[i][0], aa[i], bv0.x, acc[i][0]);
                FMA_F32X2(acc[i][1], aa[i], bv0.y, acc[i][1]);
                FMA_F32X2(acc[i][2], aa[i], bv1.x, acc[i][2]);
                FMA_F32X2(acc[i][3], aa[i], bv1.y, acc[i][3]);
            }
        }
        __syncthreads();
    }

    float4 bfa = *(const float4*)&bfc[n0 + tx * 8];
    float4 bfb = *(const float4*)&bfc[n0 + tx * 8 + 4];
#pragma unroll
    for (int i = 0; i < 4; i++) {
        float c0, c1, c2, c3, c4, c5, c6, c7;
        asm("mov.b64 {%0, %1}, %2;" : "=f"(c0), "=f"(c1) : "l"(acc[i][0]));
        asm("mov.b64 {%0, %1}, %2;" : "=f"(c2), "=f"(c3) : "l"(acc[i][1]));
        asm("mov.b64 {%0, %1}, %2;" : "=f"(c4), "=f"(c5) : "l"(acc[i][2]));
        asm("mov.b64 {%0, %1}, %2;" : "=f"(c6), "=f"(c7) : "l"(acc[i][3]));
        float4 o0 = {c0 + bfa.x, c1 + bfa.y, c2 + bfa.z, c3 + bfa.w};
        float4 o1 = {c4 + bfb.x, c5 + bfb.y, c6 + bfb.z, c7 + bfb.w};
        size_t base = (size_t)(m0 + ty * 4 + i) * Vn + n0 + tx * 8;
        *(float4*)&logits[base] = o0;
        *(float4*)&logits[base + 4] = o1;
    }
}

// ---------------- launch ----------------
extern "C" void kernel_launch(void* const* d_in, const int* in_sizes, int n_in,
                              void* d_out, int out_size) {
    const void* x = d_in[0];
    const float* hidden = (const float*)d_in[1];
    const float* etab = (const float*)d_in[2];
    const float* W_ih = (const float*)d_in[3];
    const float* W_hh = (const float*)d_in[4];
    const float* b_ih = (const float*)d_in[5];
    const float* b_hh = (const float*)d_in[6];
    const float* W1 = (const float*)d_in[7];
    const float* W2 = (const float*)d_in[8];
    const float* v = (const float*)d_in[9];
    const float* Wp = (const float*)d_in[10];
    const float* bp = (const float*)d_in[11];
    const float* Wfc = (const float*)d_in[12];
    const float* bfc = (const float*)d_in[13];

    float* out = (float*)d_out;
    float* out_logits = out;                         // (B,T,V)
    float* out_hidden = out + (size_t)Bn * Tn * Vn;  // (1,B,H)
    float* out_weights = out_hidden + Bn * Hn;       // (B,T,T)

    k_embed<<<Bn * Tn, 128>>>((const unsigned*)x, etab, W_ih, b_ih, b_hh);
    k_rnn<<<Bn, 128>>>(hidden, W_hh, out_hidden);
    k_qk<<<dim3(8, 32), 128>>>(W1, W2);
    k_attn<<<dim3(128, Bn), 256>>>(v, Wp, bp, out_weights);
    k_logits<<<dim3(Vn / BN, (Bn * Tn) / BM), 256>>>(Wfc, bfc, out_logits);
}

// round 11
// speedup vs baseline: 1.6957x; 1.6957x over previous
#include <cuda_runtime.h>

#define Tn 512
#define Bn 2
#define Hn 128
#define En 32
#define Vn 32000

// ---------------- scratch (no allocations allowed) ----------------
__device__ __align__(16) float g_xp[Bn * Tn * Hn];    // input projections + biases
__device__ __align__(16) float g_rnn[Bn * Tn * Hn];   // RNN outputs
__device__ __align__(16) float g_q[Bn * Tn * Hn];     // query = rnn @ W1^T
__device__ __align__(16) float g_k[Bn * Tn * Hn];     // keys  = rnn @ W2^T
__device__ __align__(16) float g_proj[Bn * Tn * Hn];  // relu([rnn,ctx] @ Wp^T + bp)

// ---------------- f32x2 packed-FMA helpers (SASS FFMA2, PTX-only) ----------------
#define FMA_F32X2(d, a, b, c) \
    asm("fma.rn.f32x2 %0, %1, %2, %3;" : "=l"(d) : "l"(a), "l"(b), "l"(c))
#define PACK_DUP_F32X2(d, x) \
    asm("mov.b64 %0, {%1, %1};" : "=l"(d) : "f"(x))
__device__ __forceinline__ float f2sum(unsigned long long p) {
    float lo, hi;
    asm("mov.b64 {%0, %1}, %2;" : "=f"(lo), "=f"(hi) : "l"(p));
    return lo + hi;
}

// accurate MUFU tanh (~1e-6 rel err): rare-fallback path only
__device__ __forceinline__ float fast_tanh(float x) {
    x = fminf(fmaxf(x, -15.f), 15.f);
    float e = __expf(2.f * x);
    return __fdividef(e - 1.f, e + 1.f);
}

// Taylor tanh on FMA pipe: abs err <= 1.2e-5 for |x| <= 0.55
#define TANH_C1 (-0.33333333f)
#define TANH_C2 (0.13333334f)
#define TANH_C3 (-0.05396825f)
#define TANH_C4 (0.02186949f)
__device__ __forceinline__ float poly_tanh(float x) {
    float u = x * x;
    float p = fmaf(u, TANH_C4, TANH_C3);
    p = fmaf(u, p, TANH_C2);
    p = fmaf(u, p, TANH_C1);
    p = fmaf(u, p, 1.0f);
    return x * p;
}

// ---------------- K1: embedding + input projection (detect folded in) ----------------
__global__ void k_embed(const unsigned* __restrict__ xw,
                        const float* __restrict__ etab,
                        const float* __restrict__ W_ih,
                        const float* __restrict__ b_ih,
                        const float* __restrict__ b_hh) {
    int bt = blockIdx.x;
    int h = threadIdx.x;
    int nz = 0;
    for (int i = threadIdx.x; i < 512; i += 128)
        nz |= (xw[2 * i + 1] != 0u);
    int is32 = __syncthreads_or(nz);

    __shared__ float emb[En];
    __shared__ int sidx;
    if (threadIdx.x == 0) {
        long long idx;
        if (is32) idx = (long long)(((const int*)xw)[bt]);
        else      idx = ((const long long*)xw)[bt];
        sidx = (int)idx;
    }
    __syncthreads();
    if (h < En) emb[h] = etab[(long long)sidx * En + h];
    __syncthreads();
    float acc = b_ih[h] + b_hh[h];
#pragma unroll
    for (int e = 0; e < En; e++) acc = fmaf(emb[e], W_ih[h * En + e], acc);
    g_xp[bt * Hn + h] = acc;
}

// ---------------- K2: RNN scan — broadcast LDS + FFMA2 ----------------
__global__ void __launch_bounds__(128, 1) k_rnn(const float* __restrict__ hidden,
                                                const float* __restrict__ W_hh,
                                                float* __restrict__ out_hidden) {
    int b = blockIdx.x;
    int j = threadIdx.x;
    unsigned long long w2[64];
    const unsigned long long* wrow = (const unsigned long long*)(W_hh + j * Hn);
#pragma unroll
    for (int q = 0; q < 64; q++) w2[q] = wrow[q];

    __shared__ __align__(16) float hbuf[2][Hn];
    hbuf[0][j] = hidden[b * Hn + j];
    __syncthreads();

    const float* xp = g_xp + b * Tn * Hn;
    float* rnn = g_rnn + b * Tn * Hn;
    float xv_next = xp[j];
    for (int t = 0; t < Tn; t++) {
        float xv = xv_next;
        if (t + 1 < Tn) xv_next = xp[(t + 1) * Hn + j];
        const ulonglong2* h2 = (const ulonglong2*)hbuf[t & 1];
        unsigned long long a0 = 0ull, a1 = 0ull, a2 = 0ull, a3 = 0ull;
#pragma unroll
        for (int q = 0; q < 32; q += 2) {
            ulonglong2 hv0 = h2[q];
            ulonglong2 hv1 = h2[q + 1];
            FMA_F32X2(a0, w2[2 * q + 0], hv0.x, a0);
            FMA_F32X2(a1, w2[2 * q + 1], hv0.y, a1);
            FMA_F32X2(a2, w2[2 * q + 2], hv1.x, a2);
            FMA_F32X2(a3, w2[2 * q + 3], hv1.y, a3);
        }
        float s = (f2sum(a0) + f2sum(a1)) + (f2sum(a2) + f2sum(a3)) + xv;
        float hn = poly_tanh(s);
        if (__any_sync(0xffffffffu, fabsf(s) > 0.55f)) hn = fast_tanh(s);
        hbuf[(t + 1) & 1][j] = hn;
        rnn[t * Hn + j] = hn;
        __syncthreads();
    }
    out_hidden[b * Hn + j] = hbuf[0][j];
}

// ---------------- K3: q/k projections, 32x32 tiles ----------------
__global__ void __launch_bounds__(128) k_qk(const float* __restrict__ W1,
                                            const float* __restrict__ W2) {
    __shared__ float a_s[128][34];
    __shared__ float b_s[128][36];
    int tid = threadIdx.x;
    int tx = tid & 7, ty = tid >> 3;
    int n0 = blockIdx.x * 32, m0 = blockIdx.y * 32;
    const float* W = (n0 < Hn) ? W1 : W2;
    int nb = n0 & (Hn - 1);

    for (int idx = tid; idx < 32 * 128; idx += 128) {
        int r = idx >> 7, k = idx & 127;
        a_s[k][r] = g_rnn[(m0 + r) * Hn + k];
        b_s[k][r] = W[(nb + r) * Hn + k];
    }
    __syncthreads();

    float acc[2][4];
#pragma unroll
    for (int i = 0; i < 2; i++)
#pragma unroll
        for (int jj = 0; jj < 4; jj++) acc[i][jj] = 0.f;
#pragma unroll 4
    for (int k = 0; k < 128; k++) {
        float2 av = *(const float2*)&a_s[k][ty * 2];
        float4 bv = *(const float4*)&b_s[k][tx * 4];
        acc[0][0] = fmaf(av.x, bv.x, acc[0][0]);
        acc[0][1] = fmaf(av.x, bv.y, acc[0][1]);
        acc[0][2] = fmaf(av.x, bv.z, acc[0][2]);
        acc[0][3] = fmaf(av.x, bv.w, acc[0][3]);
        acc[1][0] = fmaf(av.y, bv.x, acc[1][0]);
        acc[1][1] = fmaf(av.y, bv.y, acc[1][1]);
        acc[1][2] = fmaf(av.y, bv.z, acc[1][2]);
        acc[1][3] = fmaf(av.y, bv.w, acc[1][3]);
    }
    float* dst = (n0 < Hn) ? g_q : g_k;
#pragma unroll
    for (int i = 0; i < 2; i++) {
        float4 o = {acc[i][0], acc[i][1], acc[i][2], acc[i][3]};
        *(float4*)&dst[(m0 + ty * 2 + i) * Hn + nb + tx * 4] = o;
    }
}

// ---------------- K4: attention — thread-per-score, prefetch double-buffered tiles ----------------
// grid 1024 (one (b,t) per block). 64-row k-chunks in smem; chunk c+1 is
// LDG-prefetched into registers during chunk c's compute and STS'd after the
// barrier (single smem buffer). Scores: thread (sl,hg) = score row sl, 32-h
// quarter hg; straight-line float4 loop, no shuffles.
__global__ void __launch_bounds__(256) k_attn(const float* __restrict__ v,
                                              const float* __restrict__ Wp,
                                              const float* __restrict__ bp,
                                              float* __restrict__ out_w) {
    int bt = blockIdx.x;
    int b = bt >> 9, t = bt & 511;
    int tid = threadIdx.x;
    int sl = tid & 63, hg = tid >> 6;
    __shared__ float ks[64][132];  // 132: float4-aligned rows, conflict-free columns
    __shared__ float q_s[Hn], v_s[Hn], r_s[Hn], ctx_s[Hn];
    __shared__ float sc[Tn];
    __shared__ float red[256];
    if (tid < Hn) {
        q_s[tid] = g_q[bt * Hn + tid];
        v_s[tid] = v[tid];
        r_s[tid] = g_rnn[bt * Hn + tid];
    }
    const float4* gk4 = (const float4*)(g_k + b * Tn * Hn);  // 32 float4 per row
    // fill chunk 0 (rows 0..63 always in-bounds: no guards)
#pragma unroll
    for (int i = 0; i < 8; i++) {
        int lin = tid + i * 256;
        int r = lin >> 5, c4 = lin & 31;
        *(float4*)&ks[r][c4 * 4] = gk4[(size_t)r * 32 + c4];
    }
    __syncthreads();

    int nch = (t >> 6) + 1;
    for (int c = 0; c < nch; c++) {
        int c0 = c << 6;
        float4 pf[8];
        if (c + 1 < nch) {  // prefetch next chunk while computing this one
#pragma unroll
            for (int i = 0; i < 8; i++) {
                int lin = tid + i * 256;
                int r = lin >> 5, c4 = lin & 31;
                pf[i] = gk4[(size_t)(c0 + 64 + r) * 32 + c4];
            }
        }
        float p = 0.f;
        if (c0 + sl <= t) {
            const float4* krow4 = (const float4*)ks[sl];
            const float4* q4 = (const float4*)q_s;
            const float4* v4 = (const float4*)v_s;
            float mabs = 0.f;
#pragma unroll
            for (int i = 0; i < 8; i++) {
                int h4 = hg * 8 + i;
                float4 qq = q4[h4], kk = krow4[h4], vv = v4[h4];
                float x0 = qq.x + kk.x, x1 = qq.y + kk.y;
                float x2 = qq.z + kk.z, x3 = qq.w + kk.w;
                mabs = fmaxf(mabs, fmaxf(fmaxf(fabsf(x0), fabsf(x1)),
                                         fmaxf(fabsf(x2), fabsf(x3))));
                p = fmaf(poly_tanh(x0), vv.x, p);
                p = fmaf(poly_tanh(x1), vv.y, p);
                p = fmaf(poly_tanh(x2), vv.z, p);
                p = fmaf(poly_tanh(x3), vv.w, p);
            }
            if (mabs > 0.55f) {  // rare accurate fallback
                p = 0.f;
                for (int h = hg * 32; h < hg * 32 + 32; h++)
                    p = fmaf(fast_tanh(q_s[h] + ks[sl][h]), v_s[h], p);
            }
        }
        red[tid] = p;
        __syncthreads();
        if (tid < 64 && c0 + tid <= t)
            sc[c0 + tid] = red[tid] + red[tid + 64] + red[tid + 128] + red[tid + 192];
        if (c + 1 < nch) {  // everyone passed the barrier: safe to overwrite ks
#pragma unroll
            for (int i = 0; i < 8; i++) {
                int lin = tid + i * 256;
                int r = lin >> 5, c4 = lin & 31;
                *(float4*)&ks[r][c4 * 4] = pf[i];
            }
        }
        __syncthreads();
    }

    // softmax over [0, t]
    float m = -1e30f;
    for (int s = tid; s <= t; s += 256) m = fmaxf(m, sc[s]);
    red[tid] = m;
    __syncthreads();
    for (int st = 128; st; st >>= 1) {
        if (tid < st) red[tid] = fmaxf(red[tid], red[tid + st]);
        __syncthreads();
    }
    float mx = red[0];
    __syncthreads();
    float ssum = 0.f;
    for (int s = tid; s <= t; s += 256) {
        float e = __expf(sc[s] - mx);
        sc[s] = e;
        ssum += e;
    }
    red[tid] = ssum;
    __syncthreads();
    for (int st = 128; st; st >>= 1) {
        if (tid < st) red[tid] += red[tid + st];
        __syncthreads();
    }
    float rinv = __fdividef(1.f, red[0]);
    __syncthreads();
    for (int s = tid; s < Tn; s += 256) {
        float wv = (s <= t) ? sc[s] * rinv : 0.f;
        out_w[(size_t)bt * Tn + s] = wv;
        if (s <= t) sc[s] = wv;
    }
    __syncthreads();

    // context[h] = sum_s w[s] * rnn[b,s,h]
    {
        int h = tid & 127, part = tid >> 7;
        float c = 0.f;
        for (int s = part; s <= t; s += 2)
            c = fmaf(sc[s], g_rnn[(b * Tn + s) * Hn + h], c);
        red[tid] = c;
        __syncthreads();
        if (tid < Hn) ctx_s[tid] = red[tid] + red[tid + 128];
        __syncthreads();
    }

    // proj: relu([rnn, ctx] @ Wp^T + bp)
    {
        int j = tid >> 1, half = tid & 1;
        const float* src = half ? ctx_s : r_s;
        const float* wrow = Wp + j * (2 * Hn) + half * Hn;
        float acc = 0.f;
#pragma unroll 16
        for (int k = 0; k < Hn; k++) acc = fmaf(wrow[k], src[k], acc);
        acc += __shfl_xor_sync(0xffffffffu, acc, 1);
        if (half == 0) g_proj[bt * Hn + j] = fmaxf(acc + bp[j], 0.f);
    }
}

// ---------------- K5: logits GEMM with packed f32x2 FMA (R6 form) ----------------
#define BM 64
#define BN 128
#define TK 32
#define LDA 68
#define LDB 132
__global__ void __launch_bounds__(256) k_logits(const float* __restrict__ Wfc,
                                                const float* __restrict__ bfc,
                                                float* __restrict__ logits) {
    __shared__ float a_s[TK][LDA];
    __shared__ float b_s[TK][LDB];
    int tid = threadIdx.x;
    int tx = tid & 15, ty = tid >> 4;
    int m0 = blockIdx.y * BM, n0 = blockIdx.x * BN;
    unsigned long long acc[4][4];
#pragma unroll
    for (int i = 0; i < 4; i++)
#pragma unroll
        for (int jj = 0; jj < 4; jj++) acc[i][jj] = 0ull;

    for (int kc = 0; kc < Hn / TK; kc++) {
        for (int idx = tid; idx < BM * TK; idx += 256) {
            int r = idx >> 5, k = idx & 31;
            a_s[k][r] = g_proj[(m0 + r) * Hn + kc * TK + k];
        }
        for (int idx = tid; idx < BN * TK; idx += 256) {
            int n = idx >> 5, k = idx & 31;
            b_s[k][n] = Wfc[(size_t)(n0 + n) * Hn + kc * TK + k];
        }
        __syncthreads();
#pragma unroll 8
        for (int k = 0; k < TK; k++) {
            float4 av = *(const float4*)&a_s[k][ty * 4];
            ulonglong2 bv0 = *(const ulonglong2*)&b_s[k][tx * 8];
            ulonglong2 bv1 = *(const ulonglong2*)&b_s[k][tx * 8 + 4];
            unsigned long long aa[4];
            PACK_DUP_F32X2(aa[0], av.x);
            PACK_DUP_F32X2(aa[1], av.y);
            PACK_DUP_F32X2(aa[2], av.z);
            PACK_DUP_F32X2(aa[3], av.w);
#pragma unroll
            for (int i = 0; i < 4; i++) {
                FMA_F32X2(acc[i][0], aa[i], bv0.x, acc[i][0]);
                FMA_F32X2(acc[i][1], aa[i], bv0.y, acc[i][1]);
                FMA_F32X2(acc[i][2], aa[i], bv1.x, acc[i][2]);
                FMA_F32X2(acc[i][3], aa[i], bv1.y, acc[i][3]);
            }
        }
        __syncthreads();
    }

    float4 bfa = *(const float4*)&bfc[n0 + tx * 8];
    float4 bfb = *(const float4*)&bfc[n0 + tx * 8 + 4];
#pragma unroll
    for (int i = 0; i < 4; i++) {
        float c0, c1, c2, c3, c4, c5, c6, c7;
        asm("mov.b64 {%0, %1}, %2;" : "=f"(c0), "=f"(c1) : "l"(acc[i][0]));
        asm("mov.b64 {%0, %1}, %2;" : "=f"(c2), "=f"(c3) : "l"(acc[i][1]));
        asm("mov.b64 {%0, %1}, %2;" : "=f"(c4), "=f"(c5) : "l"(acc[i][2]));
        asm("mov.b64 {%0, %1}, %2;" : "=f"(c6), "=f"(c7) : "l"(acc[i][3]));
        float4 o0 = {c0 + bfa.x, c1 + bfa.y, c2 + bfa.z, c3 + bfa.w};
        float4 o1 = {c4 + bfb.x, c5 + bfb.y, c6 + bfb.z, c7 + bfb.w};
        size_t base = (size_t)(m0 + ty * 4 + i) * Vn + n0 + tx * 8;
        *(float4*)&logits[base] = o0;
        *(float4*)&logits[base + 4] = o1;
    }
}

// ---------------- launch ----------------
extern "C" void kernel_launch(void* const* d_in, const int* in_sizes, int n_in,
                              void* d_out, int out_size) {
    const void* x = d_in[0];
    const float* hidden = (const float*)d_in[1];
    const float* etab = (const float*)d_in[2];
    const float* W_ih = (const float*)d_in[3];
    const float* W_hh = (const float*)d_in[4];
    const float* b_ih = (const float*)d_in[5];
    const float* b_hh = (const float*)d_in[6];
    const float* W1 = (const float*)d_in[7];
    const float* W2 = (const float*)d_in[8];
    const float* v = (const float*)d_in[9];
    const float* Wp = (const float*)d_in[10];
    const float* bp = (const float*)d_in[11];
    const float* Wfc = (const float*)d_in[12];
    const float* bfc = (const float*)d_in[13];

    float* out = (float*)d_out;
    float* out_logits = out;                         // (B,T,V)
    float* out_hidden = out + (size_t)Bn * Tn * Vn;  // (1,B,H)
    float* out_weights = out_hidden + Bn * Hn;       // (B,T,T)

    k_embed<<<Bn * Tn, 128>>>((const unsigned*)x, etab, W_ih, b_ih, b_hh);
    k_rnn<<<Bn, 128>>>(hidden, W_hh, out_hidden);
    k_qk<<<dim3(8, 32), 128>>>(W1, W2);
    k_attn<<<Bn * Tn, 256>>>(v, Wp, bp, out_weights);
    k_logits<<<dim3(Vn / BN, (Bn * Tn) / BM), 256>>>(Wfc, bfc, out_logits);
}

// round 12
// speedup vs baseline: 1.9591x; 1.1554x over previous
#include <cuda_runtime.h>

#define Tn 512
#define Bn 2
#define Hn 128
#define En 32
#define Vn 32000
#define KF 384   // feature dim: 3 * Hn

// ---------------- scratch (no allocations allowed) ----------------
__device__ __align__(16) float g_xp[Bn * Tn * Hn];
__device__ __align__(16) float g_rnn[Bn * Tn * Hn];
__device__ __align__(16) float g_q[Bn * Tn * Hn];
__device__ __align__(16) float g_k[Bn * Tn * Hn];
__device__ __align__(16) float g_proj[Bn * Tn * Hn];
__device__ __align__(16) float g_F[Bn * Tn * KF];   // t-side features
__device__ __align__(16) float g_G[Bn * Tn * KF];   // s-side features
__device__ float g_c[Bn * Tn];                      // c_t = sum v*A
__device__ float g_d[Bn * Tn];                      // d_s = sum v*B
__device__ __align__(16) float g_S[Bn * Tn * Tn];   // scores -> weights
__device__ __align__(16) float g_ctx[Bn * Tn * Hn]; // attention context

// ---------------- f32x2 packed-FMA helpers (SASS FFMA2, PTX-only) ----------------
#define FMA_F32X2(d, a, b, c) \
    asm("fma.rn.f32x2 %0, %1, %2, %3;" : "=l"(d) : "l"(a), "l"(b), "l"(c))
#define PACK_DUP_F32X2(d, x) \
    asm("mov.b64 %0, {%1, %1};" : "=l"(d) : "f"(x))
__device__ __forceinline__ float f2sum(unsigned long long p) {
    float lo, hi;
    asm("mov.b64 {%0, %1}, %2;" : "=f"(lo), "=f"(hi) : "l"(p));
    return lo + hi;
}

// accurate MUFU tanh (~1e-6 rel err): rare-fallback path only
__device__ __forceinline__ float fast_tanh(float x) {
    x = fminf(fmaxf(x, -15.f), 15.f);
    float e = __expf(2.f * x);
    return __fdividef(e - 1.f, e + 1.f);
}

// Taylor tanh on FMA pipe: abs err <= 1.2e-5 for |x| <= 0.55
#define TANH_C1 (-0.33333333f)
#define TANH_C2 (0.13333334f)
#define TANH_C3 (-0.05396825f)
#define TANH_C4 (0.02186949f)
__device__ __forceinline__ float poly_tanh(float x) {
    float u = x * x;
    float p = fmaf(u, TANH_C4, TANH_C3);
    p = fmaf(u, p, TANH_C2);
    p = fmaf(u, p, TANH_C1);
    p = fmaf(u, p, 1.0f);
    return x * p;
}

// ---------------- K1: embedding + input projection (detect folded in) ----------------
__global__ void k_embed(const unsigned* __restrict__ xw,
                        const float* __restrict__ etab,
                        const float* __restrict__ W_ih,
                        const float* __restrict__ b_ih,
                        const float* __restrict__ b_hh) {
    int bt = blockIdx.x;
    int h = threadIdx.x;
    int nz = 0;
    for (int i = threadIdx.x; i < 512; i += 128)
        nz |= (xw[2 * i + 1] != 0u);
    int is32 = __syncthreads_or(nz);

    __shared__ float emb[En];
    __shared__ int sidx;
    if (threadIdx.x == 0) {
        long long idx;
        if (is32) idx = (long long)(((const int*)xw)[bt]);
        else      idx = ((const long long*)xw)[bt];
        sidx = (int)idx;
    }
    __syncthreads();
    if (h < En) emb[h] = etab[(long long)sidx * En + h];
    __syncthreads();
    float acc = b_ih[h] + b_hh[h];
#pragma unroll
    for (int e = 0; e < En; e++) acc = fmaf(emb[e], W_ih[h * En + e], acc);
    g_xp[bt * Hn + h] = acc;
}

// ---------------- K2: RNN scan — broadcast LDS + FFMA2 ----------------
__global__ void __launch_bounds__(128, 1) k_rnn(const float* __restrict__ hidden,
                                                const float* __restrict__ W_hh,
                                                float* __restrict__ out_hidden) {
    int b = blockIdx.x;
    int j = threadIdx.x;
    unsigned long long w2[64];
    const unsigned long long* wrow = (const unsigned long long*)(W_hh + j * Hn);
#pragma unroll
    for (int q = 0; q < 64; q++) w2[q] = wrow[q];

    __shared__ __align__(16) float hbuf[2][Hn];
    hbuf[0][j] = hidden[b * Hn + j];
    __syncthreads();

    const float* xp = g_xp + b * Tn * Hn;
    float* rnn = g_rnn + b * Tn * Hn;
    float xv_next = xp[j];
    for (int t = 0; t < Tn; t++) {
        float xv = xv_next;
        if (t + 1 < Tn) xv_next = xp[(t + 1) * Hn + j];
        const ulonglong2* h2 = (const ulonglong2*)hbuf[t & 1];
        unsigned long long a0 = 0ull, a1 = 0ull, a2 = 0ull, a3 = 0ull;
#pragma unroll
        for (int q = 0; q < 32; q += 2) {
            ulonglong2 hv0 = h2[q];
            ulonglong2 hv1 = h2[q + 1];
            FMA_F32X2(a0, w2[2 * q + 0], hv0.x, a0);
            FMA_F32X2(a1, w2[2 * q + 1], hv0.y, a1);
            FMA_F32X2(a2, w2[2 * q + 2], hv1.x, a2);
            FMA_F32X2(a3, w2[2 * q + 3], hv1.y, a3);
        }
        float s = (f2sum(a0) + f2sum(a1)) + (f2sum(a2) + f2sum(a3)) + xv;
        float hn = poly_tanh(s);
        if (__any_sync(0xffffffffu, fabsf(s) > 0.55f)) hn = fast_tanh(s);
        hbuf[(t + 1) & 1][j] = hn;
        rnn[t * Hn + j] = hn;
        __syncthreads();
    }
    out_hidden[b * Hn + j] = hbuf[0][j];
}

// ---------------- K3: q/k projections, 32x32 tiles ----------------
__global__ void __launch_bounds__(128) k_qk(const float* __restrict__ W1,
                                            const float* __restrict__ W2) {
    __shared__ float a_s[128][34];
    __shared__ float b_s[128][36];
    int tid = threadIdx.x;
    int tx = tid & 7, ty = tid >> 3;
    int n0 = blockIdx.x * 32, m0 = blockIdx.y * 32;
    const float* W = (n0 < Hn) ? W1 : W2;
    int nb = n0 & (Hn - 1);

    for (int idx = tid; idx < 32 * 128; idx += 128) {
        int r = idx >> 7, k = idx & 127;
        a_s[k][r] = g_rnn[(m0 + r) * Hn + k];
        b_s[k][r] = W[(nb + r) * Hn + k];
    }
    __syncthreads();

    float acc[2][4];
#pragma unroll
    for (int i = 0; i < 2; i++)
#pragma unroll
        for (int jj = 0; jj < 4; jj++) acc[i][jj] = 0.f;
#pragma unroll 4
    for (int k = 0; k < 128; k++) {
        float2 av = *(const float2*)&a_s[k][ty * 2];
        float4 bv = *(const float4*)&b_s[k][tx * 4];
        acc[0][0] = fmaf(av.x, bv.x, acc[0][0]);
        acc[0][1] = fmaf(av.x, bv.y, acc[0][1]);
        acc[0][2] = fmaf(av.x, bv.z, acc[0][2]);
        acc[0][3] = fmaf(av.x, bv.w, acc[0][3]);
        acc[1][0] = fmaf(av.y, bv.x, acc[1][0]);
        acc[1][1] = fmaf(av.y, bv.y, acc[1][1]);
        acc[1][2] = fmaf(av.y, bv.z, acc[1][2]);
        acc[1][3] = fmaf(av.y, bv.w, acc[1][3]);
    }
    float* dst = (n0 < Hn) ? g_q : g_k;
#pragma unroll
    for (int i = 0; i < 2; i++) {
        float4 o = {acc[i][0], acc[i][1], acc[i][2], acc[i][3]};
        *(float4*)&dst[(m0 + ty * 2 + i) * Hn + nb + tx * 4] = o;
    }
}

// ---------------- K4a: feature maps for the separable tanh expansion ----------------
// tanh(q+k) = (A+B)(1 - AB + (AB)^2 - ...), A=tanh q, B=tanh k.  2nd order:
// score(t,s) = c_t + d_s + F(t).G(s),  F=[-vA^2, v(A^3-A), vA^2], G=[B, B^2, B^3]
__global__ void __launch_bounds__(128) k_feat(const float* __restrict__ v) {
    int bt = blockIdx.x;
    int tid = threadIdx.x;
    float q = g_q[bt * Hn + tid], k = g_k[bt * Hn + tid], vv = v[tid];
    float A = poly_tanh(q), B = poly_tanh(k);
    if (__any_sync(0xffffffffu, fmaxf(fabsf(q), fabsf(k)) > 0.55f)) {
        A = fast_tanh(q);
        B = fast_tanh(k);
    }
    float A2 = A * A, B2 = B * B;
    int fb = bt * KF + tid;
    g_F[fb] = -vv * A2;
    g_F[fb + 128] = vv * (A2 * A - A);
    g_F[fb + 256] = vv * A2;
    g_G[fb] = B;
    g_G[fb + 128] = B2;
    g_G[fb + 256] = B2 * B;

    float c = vv * A, d = vv * B;
#pragma unroll
    for (int off = 16; off; off >>= 1) {
        c += __shfl_xor_sync(0xffffffffu, c, off);
        d += __shfl_xor_sync(0xffffffffu, d, off);
    }
    __shared__ float rc[4], rd[4];
    int w = tid >> 5;
    if ((tid & 31) == 0) { rc[w] = c; rd[w] = d; }
    __syncthreads();
    if (tid == 0) {
        g_c[bt] = rc[0] + rc[1] + rc[2] + rc[3];
        g_d[bt] = rd[0] + rd[1] + rd[2] + rd[3];
    }
}

// ---------------- K4b: score GEMM  S = c + d + F.G^T  (64x64 tiles, K=384) ----------------
__global__ void __launch_bounds__(256) k_score() {
    int sx = blockIdx.x, tyb = blockIdx.y, b = blockIdx.z;
    if (sx > tyb) return;  // tile entirely in the causal-masked future
    int n0 = sx * 64, m0 = tyb * 64, boff = b * Tn;
    __shared__ float a_s[64][68];
    __shared__ float b_s[64][68];
    int tid = threadIdx.x;
    int tx = tid & 15, ty = tid >> 4;
    float acc[4][4];
#pragma unroll
    for (int i = 0; i < 4; i++)
#pragma unroll
        for (int j = 0; j < 4; j++) acc[i][j] = 0.f;

    for (int kc = 0; kc < KF / 64; kc++) {
        for (int idx = tid; idx < 64 * 64; idx += 256) {
            int r = idx >> 6, k = idx & 63;
            a_s[k][r] = g_F[(boff + m0 + r) * KF + kc * 64 + k];
            b_s[k][r] = g_G[(boff + n0 + r) * KF + kc * 64 + k];
        }
        __syncthreads();
#pragma unroll 8
        for (int k = 0; k < 64; k++) {
            float4 av = *(const float4*)&a_s[k][ty * 4];
            float4 bv = *(const float4*)&b_s[k][tx * 4];
            float a[4] = {av.x, av.y, av.z, av.w};
            float bb[4] = {bv.x, bv.y, bv.z, bv.w};
#pragma unroll
            for (int i = 0; i < 4; i++)
#pragma unroll
                for (int j = 0; j < 4; j++)
                    acc[i][j] = fmaf(a[i], bb[j], acc[i][j]);
        }
        __syncthreads();
    }
    float dv0 = g_d[boff + n0 + tx * 4], dv1 = g_d[boff + n0 + tx * 4 + 1];
    float dv2 = g_d[boff + n0 + tx * 4 + 2], dv3 = g_d[boff + n0 + tx * 4 + 3];
#pragma unroll
    for (int i = 0; i < 4; i++) {
        float ci = g_c[boff + m0 + ty * 4 + i];
        float4 o = {acc[i][0] + ci + dv0, acc[i][1] + ci + dv1,
                    acc[i][2] + ci + dv2, acc[i][3] + ci + dv3};
        *(float4*)&g_S[(size_t)(boff + m0 + ty * 4 + i) * Tn + n0 + tx * 4] = o;
    }
}

// ---------------- K4c: causal softmax per (b,t) row ----------------
__global__ void __launch_bounds__(256) k_softmax(float* __restrict__ out_w) {
    int bt = blockIdx.x;
    int t = bt & 511;
    int tid = threadIdx.x;
    float* row = g_S + (size_t)bt * Tn;
    __shared__ float sc[Tn];
    __shared__ float red[256];

    float m = -1e30f;
    for (int s = tid; s <= t; s += 256) m = fmaxf(m, row[s]);
    red[tid] = m;
    __syncthreads();
    for (int st = 128; st; st >>= 1) {
        if (tid < st) red[tid] = fmaxf(red[tid], red[tid + st]);
        __syncthreads();
    }
    float mx = red[0];
    __syncthreads();
    float ssum = 0.f;
    for (int s = tid; s <= t; s += 256) {
        float e = __expf(row[s] - mx);
        sc[s] = e;
        ssum += e;
    }
    red[tid] = ssum;
    __syncthreads();
    for (int st = 128; st; st >>= 1) {
        if (tid < st) red[tid] += red[tid + st];
        __syncthreads();
    }
    float rinv = __fdividef(1.f, red[0]);
    __syncthreads();
    for (int s = tid; s < Tn; s += 256) {
        float wv = (s <= t) ? sc[s] * rinv : 0.f;
        out_w[(size_t)bt * Tn + s] = wv;
        row[s] = wv;  // zeros beyond t: ctx GEMM can run full K
    }
}

// ---------------- K4d: context GEMM  ctx = W . rnn  (32x32 tiles, K=512) ----------------
__global__ void __launch_bounds__(128) k_ctx() {
    int n0 = blockIdx.x * 32;  // h
    int m0 = blockIdx.y * 32;  // t
    int b = blockIdx.z;
    __shared__ float a_s[128][34];
    __shared__ float b_s[128][36];
    int tid = threadIdx.x;
    int tx = tid & 7, ty = tid >> 3;
    float acc[2][4];
#pragma unroll
    for (int i = 0; i < 2; i++)
#pragma unroll
        for (int j = 0; j < 4; j++) acc[i][j] = 0.f;

    for (int kc = 0; kc < 4; kc++) {
        for (int idx = tid; idx < 32 * 128; idx += 128) {
            int r = idx >> 7, k = idx & 127;  // k-fastest: coalesced (k contiguous)
            a_s[k][r] = g_S[(size_t)(b * Tn + m0 + r) * Tn + kc * 128 + k];
        }
        for (int idx = tid; idx < 32 * 128; idx += 128) {
            int k = idx >> 5, r = idx & 31;   // r-fastest: coalesced (h contiguous)
            b_s[k][r] = g_rnn[(b * Tn + kc * 128 + k) * Hn + n0 + r];
        }
        __syncthreads();
#pragma unroll 4
        for (int k = 0; k < 128; k++) {
            float2 av = *(const float2*)&a_s[k][ty * 2];
            float4 bv = *(const float4*)&b_s[k][tx * 4];
            acc[0][0] = fmaf(av.x, bv.x, acc[0][0]);
            acc[0][1] = fmaf(av.x, bv.y, acc[0][1]);
            acc[0][2] = fmaf(av.x, bv.z, acc[0][2]);
            acc[0][3] = fmaf(av.x, bv.w, acc[0][3]);
            acc[1][0] = fmaf(av.y, bv.x, acc[1][0]);
            acc[1][1] = fmaf(av.y, bv.y, acc[1][1]);
            acc[1][2] = fmaf(av.y, bv.z, acc[1][2]);
            acc[1][3] = fmaf(av.y, bv.w, acc[1][3]);
        }
        __syncthreads();
    }
#pragma unroll
    for (int i = 0; i < 2; i++) {
        float4 o = {acc[i][0], acc[i][1], acc[i][2], acc[i][3]};
        *(float4*)&g_ctx[(b * Tn + m0 + ty * 2 + i) * Hn + n0 + tx * 4] = o;
    }
}

// ---------------- K4e: proj GEMM  g_proj = relu([rnn,ctx].Wp^T + bp) ----------------
__global__ void __launch_bounds__(128) k_proj(const float* __restrict__ Wp,
                                              const float* __restrict__ bp) {
    int n0 = blockIdx.x * 32;  // j
    int m0 = blockIdx.y * 32;  // bt
    __shared__ float a_s[128][34];
    __shared__ float b_s[128][36];
    int tid = threadIdx.x;
    int tx = tid & 7, ty = tid >> 3;
    float acc[2][4];
#pragma unroll
    for (int i = 0; i < 2; i++)
#pragma unroll
        for (int j = 0; j < 4; j++) acc[i][j] = 0.f;

    for (int ch = 0; ch < 2; ch++) {
        const float* src = ch ? g_ctx : g_rnn;
        for (int idx = tid; idx < 32 * 128; idx += 128) {
            int r = idx >> 7, k = idx & 127;
            a_s[k][r] = src[(m0 + r) * Hn + k];
            b_s[k][r] = Wp[(n0 + r) * (2 * Hn) + ch * Hn + k];
        }
        __syncthreads();
#pragma unroll 4
        for (int k = 0; k < 128; k++) {
            float2 av = *(const float2*)&a_s[k][ty * 2];
            float4 bv = *(const float4*)&b_s[k][tx * 4];
            acc[0][0] = fmaf(av.x, bv.x, acc[0][0]);
            acc[0][1] = fmaf(av.x, bv.y, acc[0][1]);
            acc[0][2] = fmaf(av.x, bv.z, acc[0][2]);
            acc[0][3] = fmaf(av.x, bv.w, acc[0][3]);
            acc[1][0] = fmaf(av.y, bv.x, acc[1][0]);
            acc[1][1] = fmaf(av.y, bv.y, acc[1][1]);
            acc[1][2] = fmaf(av.y, bv.z, acc[1][2]);
            acc[1][3] = fmaf(av.y, bv.w, acc[1][3]);
        }
        __syncthreads();
    }
    float4 bpv = *(const float4*)&bp[n0 + tx * 4];
    float bb[4] = {bpv.x, bpv.y, bpv.z, bpv.w};
#pragma unroll
    for (int i = 0; i < 2; i++) {
        float4 o = {fmaxf(acc[i][0] + bb[0], 0.f), fmaxf(acc[i][1] + bb[1], 0.f),
                    fmaxf(acc[i][2] + bb[2], 0.f), fmaxf(acc[i][3] + bb[3], 0.f)};
        *(float4*)&g_proj[(m0 + ty * 2 + i) * Hn + n0 + tx * 4] = o;
    }
}

// ---------------- K5: logits GEMM with packed f32x2 FMA ----------------
#define BM 64
#define BN 128
#define TK 32
#define LDA 68
#define LDB 132
__global__ void __launch_bounds__(256) k_logits(const float* __restrict__ Wfc,
                                                const float* __restrict__ bfc,
                                                float* __restrict__ logits) {
    __shared__ float a_s[TK][LDA];
    __shared__ float b_s[TK][LDB];
    int tid = threadIdx.x;
    int tx = tid & 15, ty = tid >> 4;
    int m0 = blockIdx.y * BM, n0 = blockIdx.x * BN;
    unsigned long long acc[4][4];
#pragma unroll
    for (int i = 0; i < 4; i++)
#pragma unroll
        for (int jj = 0; jj < 4; jj++) acc[i][jj] = 0ull;

    for (int kc = 0; kc < Hn / TK; kc++) {
        for (int idx = tid; idx < BM * TK; idx += 256) {
            int r = idx >> 5, k = idx & 31;
            a_s[k][r] = g_proj[(m0 + r) * Hn + kc * TK + k];
        }
        for (int idx = tid; idx < BN * TK; idx += 256) {
            int n = idx >> 5, k = idx & 31;
            b_s[k][n] = Wfc[(size_t)(n0 + n) * Hn + kc * TK + k];
        }
        __syncthreads();
#pragma unroll 8
        for (int k = 0; k < TK; k++) {
            float4 av = *(const float4*)&a_s[k][ty * 4];
            ulonglong2 bv0 = *(const ulonglong2*)&b_s[k][tx * 8];
            ulonglong2 bv1 = *(const ulonglong2*)&b_s[k][tx * 8 + 4];
            unsigned long long aa[4];
            PACK_DUP_F32X2(aa[0], av.x);
            PACK_DUP_F32X2(aa[1], av.y);
            PACK_DUP_F32X2(aa[2], av.z);
            PACK_DUP_F32X2(aa[3], av.w);
#pragma unroll
            for (int i = 0; i < 4; i++) {
                FMA_F32X2(acc[i][0], aa[i], bv0.x, acc[i][0]);
                FMA_F32X2(acc[i][1], aa[i], bv0.y, acc[i][1]);
                FMA_F32X2(acc[i][2], aa[i], bv1.x, acc[i][2]);
                FMA_F32X2(acc[i][3], aa[i], bv1.y, acc[i][3]);
            }
        }
        __syncthreads();
    }

    float4 bfa = *(const float4*)&bfc[n0 + tx * 8];
    float4 bfb = *(const float4*)&bfc[n0 + tx * 8 + 4];
#pragma unroll
    for (int i = 0; i < 4; i++) {
        float c0, c1, c2, c3, c4, c5, c6, c7;
        asm("mov.b64 {%0, %1}, %2;" : "=f"(c0), "=f"(c1) : "l"(acc[i][0]));
        asm("mov.b64 {%0, %1}, %2;" : "=f"(c2), "=f"(c3) : "l"(acc[i][1]));
        asm("mov.b64 {%0, %1}, %2;" : "=f"(c4), "=f"(c5) : "l"(acc[i][2]));
        asm("mov.b64 {%0, %1}, %2;" : "=f"(c6), "=f"(c7) : "l"(acc[i][3]));
        float4 o0 = {c0 + bfa.x, c1 + bfa.y, c2 + bfa.z, c3 + bfa.w};
        float4 o1 = {c4 + bfb.x, c5 + bfb.y, c6 + bfb.z, c7 + bfb.w};
        size_t base = (size_t)(m0 + ty * 4 + i) * Vn + n0 + tx * 8;
        *(float4*)&logits[base] = o0;
        *(float4*)&logits[base + 4] = o1;
    }
}

// ---------------- launch ----------------
extern "C" void kernel_launch(void* const* d_in, const int* in_sizes, int n_in,
                              void* d_out, int out_size) {
    const void* x = d_in[0];
    const float* hidden = (const float*)d_in[1];
    const float* etab = (const float*)d_in[2];
    const float* W_ih = (const float*)d_in[3];
    const float* W_hh = (const float*)d_in[4];
    const float* b_ih = (const float*)d_in[5];
    const float* b_hh = (const float*)d_in[6];
    const float* W1 = (const float*)d_in[7];
    const float* W2 = (const float*)d_in[8];
    const float* v = (const float*)d_in[9];
    const float* Wp = (const float*)d_in[10];
    const float* bp = (const float*)d_in[11];
    const float* Wfc = (const float*)d_in[12];
    const float* bfc = (const float*)d_in[13];

    float* out = (float*)d_out;
    float* out_logits = out;                         // (B,T,V)
    float* out_hidden = out + (size_t)Bn * Tn * Vn;  // (1,B,H)
    float* out_weights = out_hidden + Bn * Hn;       // (B,T,T)

    k_embed<<<Bn * Tn, 128>>>((const unsigned*)x, etab, W_ih, b_ih, b_hh);
    k_rnn<<<Bn, 128>>>(hidden, W_hh, out_hidden);
    k_qk<<<dim3(8, 32), 128>>>(W1, W2);
    k_feat<<<Bn * Tn, 128>>>(v);
    k_score<<<dim3(8, 8, Bn), 256>>>();
    k_softmax<<<Bn * Tn, 256>>>(out_weights);
    k_ctx<<<dim3(4, 16, Bn), 128>>>();
    k_proj<<<dim3(4, 32), 128>>>(Wp, bp);
    k_logits<<<dim3(Vn / BN, (Bn * Tn) / BM), 256>>>(Wfc, bfc, out_logits);
}

// round 15
// speedup vs baseline: 3.1279x; 1.5966x over previous
#include <cuda_runtime.h>
#include <cuda_bf16.h>
#include <cstdint>

#define Tn 512
#define Bn 2
#define Hn 128
#define En 32
#define Vn 32000
#define KF 384   // feature dim: 3 * Hn

// ---------------- scratch (no allocations allowed) ----------------
__device__ __align__(16) float g_xp[Bn * Tn * Hn];
__device__ __align__(16) float g_rnn[Bn * Tn * Hn];
__device__ __align__(16) float g_q[Bn * Tn * Hn];
__device__ __align__(16) float g_k[Bn * Tn * Hn];
__device__ __align__(16) float g_proj[Bn * Tn * Hn];
__device__ __align__(16) float g_F[Bn * Tn * KF];
__device__ __align__(16) float g_G[Bn * Tn * KF];
__device__ float g_c[Bn * Tn];
__device__ float g_d[Bn * Tn];
__device__ __align__(16) float g_S[Bn * Tn * Tn];
__device__ __align__(16) float g_ctx[Bn * Tn * Hn];
__device__ __align__(16) __nv_bfloat16 g_wh[(size_t)Vn * Hn];  // Wfc hi
__device__ __align__(16) __nv_bfloat16 g_wl[(size_t)Vn * Hn];  // Wfc lo
__device__ __align__(16) __nv_bfloat16 g_ph[Bn * Tn * Hn];     // proj hi
__device__ __align__(16) __nv_bfloat16 g_pl[Bn * Tn * Hn];     // proj lo

// ---------------- f32x2 packed-FMA helpers ----------------
#define FMA_F32X2(d, a, b, c) \
    asm("fma.rn.f32x2 %0, %1, %2, %3;" : "=l"(d) : "l"(a), "l"(b), "l"(c))
__device__ __forceinline__ float f2sum(unsigned long long p) {
    float lo, hi;
    asm("mov.b64 {%0, %1}, %2;" : "=f"(lo), "=f"(hi) : "l"(p));
    return lo + hi;
}

__device__ __forceinline__ float fast_tanh(float x) {
    x = fminf(fmaxf(x, -15.f), 15.f);
    float e = __expf(2.f * x);
    return __fdividef(e - 1.f, e + 1.f);
}
#define TANH_C1 (-0.33333333f)
#define TANH_C2 (0.13333334f)
#define TANH_C3 (-0.05396825f)
#define TANH_C4 (0.02186949f)
__device__ __forceinline__ float poly_tanh(float x) {
    float u = x * x;
    float p = fmaf(u, TANH_C4, TANH_C3);
    p = fmaf(u, p, TANH_C2);
    p = fmaf(u, p, TANH_C1);
    p = fmaf(u, p, 1.0f);
    return x * p;
}

// ---------------- mma.sync / ldmatrix helpers (sm_80-era: legal on compute_103) ----------------
__device__ __forceinline__ uint32_t smem_u32(const void* p) {
    uint32_t a;
    asm("{ .reg .u64 t; cvta.to.shared.u64 t, %1; cvt.u32.u64 %0, t; }" : "=r"(a) : "l"(p));
    return a;
}
#define LDMX4(r, addr) \
    asm volatile("ldmatrix.sync.aligned.m8n8.x4.shared.b16 {%0,%1,%2,%3}, [%4];" \
        : "=r"((r)[0]), "=r"((r)[1]), "=r"((r)[2]), "=r"((r)[3]) : "r"(addr))
#define MMA16816(d, a, b) \
    asm volatile("mma.sync.aligned.m16n8k16.row.col.f32.bf16.bf16.f32 " \
        "{%0,%1,%2,%3}, {%4,%5,%6,%7}, {%8,%9}, {%0,%1,%2,%3};" \
        : "+f"((d)[0]), "+f"((d)[1]), "+f"((d)[2]), "+f"((d)[3]) \
        : "r"((a)[0]), "r"((a)[1]), "r"((a)[2]), "r"((a)[3]), "r"((b)[0]), "r"((b)[1]))

// ---------------- K1: embedding + input projection ----------------
__global__ void k_embed(const unsigned* __restrict__ xw,
                        const float* __restrict__ etab,
                        const float* __restrict__ W_ih,
                        const float* __restrict__ b_ih,
                        const float* __restrict__ b_hh) {
    int bt = blockIdx.x;
    int h = threadIdx.x;
    int nz = 0;
    for (int i = threadIdx.x; i < 512; i += 128)
        nz |= (xw[2 * i + 1] != 0u);
    int is32 = __syncthreads_or(nz);

    __shared__ float emb[En];
    __shared__ int sidx;
    if (threadIdx.x == 0) {
        long long idx;
        if (is32) idx = (long long)(((const int*)xw)[bt]);
        else      idx = ((const long long*)xw)[bt];
        sidx = (int)idx;
    }
    __syncthreads();
    if (h < En) emb[h] = etab[(long long)sidx * En + h];
    __syncthreads();
    float acc = b_ih[h] + b_hh[h];
#pragma unroll
    for (int e = 0; e < En; e++) acc = fmaf(emb[e], W_ih[h * En + e], acc);
    g_xp[bt * Hn + h] = acc;
}

// ---------------- K2: RNN scan ----------------
__global__ void __launch_bounds__(128, 1) k_rnn(const float* __restrict__ hidden,
                                                const float* __restrict__ W_hh,
                                                float* __restrict__ out_hidden) {
    int b = blockIdx.x;
    int j = threadIdx.x;
    unsigned long long w2[64];
    const unsigned long long* wrow = (const unsigned long long*)(W_hh + j * Hn);
#pragma unroll
    for (int q = 0; q < 64; q++) w2[q] = wrow[q];

    __shared__ __align__(16) float hbuf[2][Hn];
    hbuf[0][j] = hidden[b * Hn + j];
    __syncthreads();

    const float* xp = g_xp + b * Tn * Hn;
    float* rnn = g_rnn + b * Tn * Hn;
    float xv_next = xp[j];
    for (int t = 0; t < Tn; t++) {
        float xv = xv_next;
        if (t + 1 < Tn) xv_next = xp[(t + 1) * Hn + j];
        const ulonglong2* h2 = (const ulonglong2*)hbuf[t & 1];
        unsigned long long a0 = 0ull, a1 = 0ull, a2 = 0ull, a3 = 0ull;
#pragma unroll
        for (int q = 0; q < 32; q += 2) {
            ulonglong2 hv0 = h2[q];
            ulonglong2 hv1 = h2[q + 1];
            FMA_F32X2(a0, w2[2 * q + 0], hv0.x, a0);
            FMA_F32X2(a1, w2[2 * q + 1], hv0.y, a1);
            FMA_F32X2(a2, w2[2 * q + 2], hv1.x, a2);
            FMA_F32X2(a3, w2[2 * q + 3], hv1.y, a3);
        }
        float s = (f2sum(a0) + f2sum(a1)) + (f2sum(a2) + f2sum(a3)) + xv;
        float hn = poly_tanh(s);
        if (__any_sync(0xffffffffu, fabsf(s) > 0.55f)) hn = fast_tanh(s);
        hbuf[(t + 1) & 1][j] = hn;
        rnn[t * Hn + j] = hn;
        __syncthreads();
    }
    out_hidden[b * Hn + j] = hbuf[0][j];
}

// ---------------- K3: q/k projections ----------------
__global__ void __launch_bounds__(128) k_qk(const float* __restrict__ W1,
                                            const float* __restrict__ W2) {
    __shared__ float a_s[128][34];
    __shared__ float b_s[128][36];
    int tid = threadIdx.x;
    int tx = tid & 7, ty = tid >> 3;
    int n0 = blockIdx.x * 32, m0 = blockIdx.y * 32;
    const float* W = (n0 < Hn) ? W1 : W2;
    int nb = n0 & (Hn - 1);

    for (int idx = tid; idx < 32 * 128; idx += 128) {
        int r = idx >> 7, k = idx & 127;
        a_s[k][r] = g_rnn[(m0 + r) * Hn + k];
        b_s[k][r] = W[(nb + r) * Hn + k];
    }
    __syncthreads();

    float acc[2][4];
#pragma unroll
    for (int i = 0; i < 2; i++)
#pragma unroll
        for (int jj = 0; jj < 4; jj++) acc[i][jj] = 0.f;
#pragma unroll 4
    for (int k = 0; k < 128; k++) {
        float2 av = *(const float2*)&a_s[k][ty * 2];
        float4 bv = *(const float4*)&b_s[k][tx * 4];
        acc[0][0] = fmaf(av.x, bv.x, acc[0][0]);
        acc[0][1] = fmaf(av.x, bv.y, acc[0][1]);
        acc[0][2] = fmaf(av.x, bv.z, acc[0][2]);
        acc[0][3] = fmaf(av.x, bv.w, acc[0][3]);
        acc[1][0] = fmaf(av.y, bv.x, acc[1][0]);
        acc[1][1] = fmaf(av.y, bv.y, acc[1][1]);
        acc[1][2] = fmaf(av.y, bv.z, acc[1][2]);
        acc[1][3] = fmaf(av.y, bv.w, acc[1][3]);
    }
    float* dst = (n0 < Hn) ? g_q : g_k;
#pragma unroll
    for (int i = 0; i < 2; i++) {
        float4 o = {acc[i][0], acc[i][1], acc[i][2], acc[i][3]};
        *(float4*)&dst[(m0 + ty * 2 + i) * Hn + nb + tx * 4] = o;
    }
}

// ---------------- K4a: separable tanh features ----------------
__global__ void __launch_bounds__(128) k_feat(const float* __restrict__ v) {
    int bt = blockIdx.x;
    int tid = threadIdx.x;
    float q = g_q[bt * Hn + tid], k = g_k[bt * Hn + tid], vv = v[tid];
    float A = poly_tanh(q), B = poly_tanh(k);
    if (__any_sync(0xffffffffu, fmaxf(fabsf(q), fabsf(k)) > 0.55f)) {
        A = fast_tanh(q);
        B = fast_tanh(k);
    }
    float A2 = A * A, B2 = B * B;
    int fb = bt * KF + tid;
    g_F[fb] = -vv * A2;
    g_F[fb + 128] = vv * (A2 * A - A);
    g_F[fb + 256] = vv * A2;
    g_G[fb] = B;
    g_G[fb + 128] = B2;
    g_G[fb + 256] = B2 * B;

    float c = vv * A, d = vv * B;
#pragma unroll
    for (int off = 16; off; off >>= 1) {
        c += __shfl_xor_sync(0xffffffffu, c, off);
        d += __shfl_xor_sync(0xffffffffu, d, off);
    }
    __shared__ float rc[4], rd[4];
    int w = tid >> 5;
    if ((tid & 31) == 0) { rc[w] = c; rd[w] = d; }
    __syncthreads();
    if (tid == 0) {
        g_c[bt] = rc[0] + rc[1] + rc[2] + rc[3];
        g_d[bt] = rd[0] + rd[1] + rd[2] + rd[3];
    }
}

// ---------------- K4b: score GEMM ----------------
__global__ void __launch_bounds__(256) k_score() {
    int sx = blockIdx.x, tyb = blockIdx.y, b = blockIdx.z;
    if (sx > tyb) return;
    int n0 = sx * 64, m0 = tyb * 64, boff = b * Tn;
    __shared__ float a_s[64][68];
    __shared__ float b_s[64][68];
    int tid = threadIdx.x;
    int tx = tid & 15, ty = tid >> 4;
    float acc[4][4];
#pragma unroll
    for (int i = 0; i < 4; i++)
#pragma unroll
        for (int j = 0; j < 4; j++) acc[i][j] = 0.f;

    for (int kc = 0; kc < KF / 64; kc++) {
        for (int idx = tid; idx < 64 * 64; idx += 256) {
            int r = idx >> 6, k = idx & 63;
            a_s[k][r] = g_F[(boff + m0 + r) * KF + kc * 64 + k];
            b_s[k][r] = g_G[(boff + n0 + r) * KF + kc * 64 + k];
        }
        __syncthreads();
#pragma unroll 8
        for (int k = 0; k < 64; k++) {
            float4 av = *(const float4*)&a_s[k][ty * 4];
            float4 bv = *(const float4*)&b_s[k][tx * 4];
            float a[4] = {av.x, av.y, av.z, av.w};
            float bb[4] = {bv.x, bv.y, bv.z, bv.w};
#pragma unroll
            for (int i = 0; i < 4; i++)
#pragma unroll
                for (int j = 0; j < 4; j++)
                    acc[i][j] = fmaf(a[i], bb[j], acc[i][j]);
        }
        __syncthreads();
    }
    float dv0 = g_d[boff + n0 + tx * 4], dv1 = g_d[boff + n0 + tx * 4 + 1];
    float dv2 = g_d[boff + n0 + tx * 4 + 2], dv3 = g_d[boff + n0 + tx * 4 + 3];
#pragma unroll
    for (int i = 0; i < 4; i++) {
        float ci = g_c[boff + m0 + ty * 4 + i];
        float4 o = {acc[i][0] + ci + dv0, acc[i][1] + ci + dv1,
                    acc[i][2] + ci + dv2, acc[i][3] + ci + dv3};
        *(float4*)&g_S[(size_t)(boff + m0 + ty * 4 + i) * Tn + n0 + tx * 4] = o;
    }
}

// ---------------- K4c: causal softmax ----------------
__global__ void __launch_bounds__(256) k_softmax(float* __restrict__ out_w) {
    int bt = blockIdx.x;
    int t = bt & 511;
    int tid = threadIdx.x;
    float* row = g_S + (size_t)bt * Tn;
    __shared__ float sc[Tn];
    __shared__ float red[256];

    float m = -1e30f;
    for (int s = tid; s <= t; s += 256) m = fmaxf(m, row[s]);
    red[tid] = m;
    __syncthreads();
    for (int st = 128; st; st >>= 1) {
        if (tid < st) red[tid] = fmaxf(red[tid], red[tid + st]);
        __syncthreads();
    }
    float mx = red[0];
    __syncthreads();
    float ssum = 0.f;
    for (int s = tid; s <= t; s += 256) {
        float e = __expf(row[s] - mx);
        sc[s] = e;
        ssum += e;
    }
    red[tid] = ssum;
    __syncthreads();
    for (int st = 128; st; st >>= 1) {
        if (tid < st) red[tid] += red[tid + st];
        __syncthreads();
    }
    float rinv = __fdividef(1.f, red[0]);
    __syncthreads();
    for (int s = tid; s < Tn; s += 256) {
        float wv = (s <= t) ? sc[s] * rinv : 0.f;
        out_w[(size_t)bt * Tn + s] = wv;
        row[s] = wv;
    }
}

// ---------------- K4d: context GEMM ----------------
__global__ void __launch_bounds__(128) k_ctx() {
    int n0 = blockIdx.x * 32;
    int m0 = blockIdx.y * 32;
    int b = blockIdx.z;
    __shared__ float a_s[128][34];
    __shared__ float b_s[128][36];
    int tid = threadIdx.x;
    int tx = tid & 7, ty = tid >> 3;
    float acc[2][4];
#pragma unroll
    for (int i = 0; i < 2; i++)
#pragma unroll
        for (int j = 0; j < 4; j++) acc[i][j] = 0.f;

    for (int kc = 0; kc < 4; kc++) {
        for (int idx = tid; idx < 32 * 128; idx += 128) {
            int r = idx >> 7, k = idx & 127;
            a_s[k][r] = g_S[(size_t)(b * Tn + m0 + r) * Tn + kc * 128 + k];
        }
        for (int idx = tid; idx < 32 * 128; idx += 128) {
            int k = idx >> 5, r = idx & 31;
            b_s[k][r] = g_rnn[(b * Tn + kc * 128 + k) * Hn + n0 + r];
        }
        __syncthreads();
#pragma unroll 4
        for (int k = 0; k < 128; k++) {
            float2 av = *(const float2*)&a_s[k][ty * 2];
            float4 bv = *(const float4*)&b_s[k][tx * 4];
            acc[0][0] = fmaf(av.x, bv.x, acc[0][0]);
            acc[0][1] = fmaf(av.x, bv.y, acc[0][1]);
            acc[0][2] = fmaf(av.x, bv.z, acc[0][2]);
            acc[0][3] = fmaf(av.x, bv.w, acc[0][3]);
            acc[1][0] = fmaf(av.y, bv.x, acc[1][0]);
            acc[1][1] = fmaf(av.y, bv.y, acc[1][1]);
            acc[1][2] = fmaf(av.y, bv.z, acc[1][2]);
            acc[1][3] = fmaf(av.y, bv.w, acc[1][3]);
        }
        __syncthreads();
    }
#pragma unroll
    for (int i = 0; i < 2; i++) {
        float4 o = {acc[i][0], acc[i][1], acc[i][2], acc[i][3]};
        *(float4*)&g_ctx[(b * Tn + m0 + ty * 2 + i) * Hn + n0 + tx * 4] = o;
    }
}

// ---------------- K4e: proj GEMM (+ bf16 hi/lo copies for the MMA logits) ----------------
__global__ void __launch_bounds__(128) k_proj(const float* __restrict__ Wp,
                                              const float* __restrict__ bp) {
    int n0 = blockIdx.x * 32;
    int m0 = blockIdx.y * 32;
    __shared__ float a_s[128][34];
    __shared__ float b_s[128][36];
    int tid = threadIdx.x;
    int tx = tid & 7, ty = tid >> 3;
    float acc[2][4];
#pragma unroll
    for (int i = 0; i < 2; i++)
#pragma unroll
        for (int j = 0; j < 4; j++) acc[i][j] = 0.f;

    for (int ch = 0; ch < 2; ch++) {
        const float* src = ch ? g_ctx : g_rnn;
        for (int idx = tid; idx < 32 * 128; idx += 128) {
            int r = idx >> 7, k = idx & 127;
            a_s[k][r] = src[(m0 + r) * Hn + k];
            b_s[k][r] = Wp[(n0 + r) * (2 * Hn) + ch * Hn + k];
        }
        __syncthreads();
#pragma unroll 4
        for (int k = 0; k < 128; k++) {
            float2 av = *(const float2*)&a_s[k][ty * 2];
            float4 bv = *(const float4*)&b_s[k][tx * 4];
            acc[0][0] = fmaf(av.x, bv.x, acc[0][0]);
            acc[0][1] = fmaf(av.x, bv.y, acc[0][1]);
            acc[0][2] = fmaf(av.x, bv.z, acc[0][2]);
            acc[0][3] = fmaf(av.x, bv.w, acc[0][3]);
            acc[1][0] = fmaf(av.y, bv.x, acc[1][0]);
            acc[1][1] = fmaf(av.y, bv.y, acc[1][1]);
            acc[1][2] = fmaf(av.y, bv.z, acc[1][2]);
            acc[1][3] = fmaf(av.y, bv.w, acc[1][3]);
        }
        __syncthreads();
    }
    float4 bpv = *(const float4*)&bp[n0 + tx * 4];
    float bb[4] = {bpv.x, bpv.y, bpv.z, bpv.w};
#pragma unroll
    for (int i = 0; i < 2; i++) {
        float4 o = {fmaxf(acc[i][0] + bb[0], 0.f), fmaxf(acc[i][1] + bb[1], 0.f),
                    fmaxf(acc[i][2] + bb[2], 0.f), fmaxf(acc[i][3] + bb[3], 0.f)};
        int row = m0 + ty * 2 + i, cb = n0 + tx * 4;
        *(float4*)&g_proj[row * Hn + cb] = o;
        // bf16 hi/lo split of proj for the tensor-core logits GEMM
        __nv_bfloat16 h0 = __float2bfloat16(o.x), h1 = __float2bfloat16(o.y);
        __nv_bfloat16 h2 = __float2bfloat16(o.z), h3 = __float2bfloat16(o.w);
        __nv_bfloat162 hh0, hh1, ll0, ll1;
        hh0.x = h0; hh0.y = h1; hh1.x = h2; hh1.y = h3;
        ll0.x = __float2bfloat16(o.x - __bfloat162float(h0));
        ll0.y = __float2bfloat16(o.y - __bfloat162float(h1));
        ll1.x = __float2bfloat16(o.z - __bfloat162float(h2));
        ll1.y = __float2bfloat16(o.w - __bfloat162float(h3));
        *(__nv_bfloat162*)&g_ph[row * Hn + cb] = hh0;
        *(__nv_bfloat162*)&g_ph[row * Hn + cb + 2] = hh1;
        *(__nv_bfloat162*)&g_pl[row * Hn + cb] = ll0;
        *(__nv_bfloat162*)&g_pl[row * Hn + cb + 2] = ll1;
    }
}

// ---------------- K5a: Wfc fp32 -> bf16 hi/lo split ----------------
__global__ void __launch_bounds__(256) k_wconv(const float* __restrict__ Wfc) {
    size_t i = (size_t)blockIdx.x * 256 + threadIdx.x;  // float4 index
    float4 w = ((const float4*)Wfc)[i];
    __nv_bfloat16 h0 = __float2bfloat16(w.x), h1 = __float2bfloat16(w.y);
    __nv_bfloat16 h2 = __float2bfloat16(w.z), h3 = __float2bfloat16(w.w);
    __nv_bfloat162 hh0, hh1, ll0, ll1;
    hh0.x = h0; hh0.y = h1; hh1.x = h2; hh1.y = h3;
    ll0.x = __float2bfloat16(w.x - __bfloat162float(h0));
    ll0.y = __float2bfloat16(w.y - __bfloat162float(h1));
    ll1.x = __float2bfloat16(w.z - __bfloat162float(h2));
    ll1.y = __float2bfloat16(w.w - __bfloat162float(h3));
    ((__nv_bfloat162*)g_wh)[i * 2] = hh0;
    ((__nv_bfloat162*)g_wh)[i * 2 + 1] = hh1;
    ((__nv_bfloat162*)g_wl)[i * 2] = ll0;
    ((__nv_bfloat162*)g_wl)[i * 2 + 1] = ll1;
}

// ---------------- K5b: logits GEMM on mma.sync bf16 split precision ----------------
// C[1024,32000] = proj @ Wfc^T + bfc.  128x128 tile, 8 warps (4m x 2n),
// warp tile 32x64, full K=128 staged in smem once.
// Rows padded to 272B: ldmatrix 8-row phases advance 4 banks -> conflict-free.
#define LROW 272
#define SM_AH 0
#define SM_AL 34816
#define SM_BH 69632
#define SM_BL 104448
#define SM_TOT 139264
__global__ void __launch_bounds__(256) k_logits_mma(const float* __restrict__ bfc,
                                                    float* __restrict__ logits) {
    extern __shared__ char smem[];
    uint32_t sb = smem_u32(smem);
    int tid = threadIdx.x;
    int lane = tid & 31, wid = tid >> 5;
    int wr = wid & 3, wc = wid >> 2;
    int m0 = blockIdx.y * 128, n0 = blockIdx.x * 128;

    // stage all four tiles (each 128 rows x 256B payload, 272B stride)
    for (int idx = tid; idx < 128 * 16; idx += 256) {
        int row = idx >> 4, q = idx & 15;
        *(uint4*)(smem + SM_AH + row * LROW + q * 16) =
            ((const uint4*)(g_ph + (size_t)(m0 + row) * Hn))[q];
        *(uint4*)(smem + SM_AL + row * LROW + q * 16) =
            ((const uint4*)(g_pl + (size_t)(m0 + row) * Hn))[q];
        *(uint4*)(smem + SM_BH + row * LROW + q * 16) =
            ((const uint4*)(g_wh + (size_t)(n0 + row) * Hn))[q];
        *(uint4*)(smem + SM_BL + row * LROW + q * 16) =
            ((const uint4*)(g_wl + (size_t)(n0 + row) * Hn))[q];
    }
    __syncthreads();

    float d[2][8][4];
#pragma unroll
    for (int mf = 0; mf < 2; mf++)
#pragma unroll
        for (int nf = 0; nf < 8; nf++)
#pragma unroll
            for (int e = 0; e < 4; e++) d[mf][nf][e] = 0.f;

    int lrow = lane & 15;
    int lkoff = (lane >> 4) * 16;

#pragma unroll
    for (int ks = 0; ks < 8; ks++) {
        uint32_t ah[2][4], al[2][4];
#pragma unroll
        for (int mf = 0; mf < 2; mf++) {
            uint32_t ad = sb + SM_AH + (wr * 32 + mf * 16 + lrow) * LROW + ks * 32 + lkoff;
            LDMX4(ah[mf], ad);
            LDMX4(al[mf], ad + (SM_AL - SM_AH));
        }
#pragma unroll
        for (int p = 0; p < 4; p++) {
            uint32_t bd = sb + SM_BH + (wc * 64 + p * 16 + lrow) * LROW + ks * 32 + lkoff;
            uint32_t th[4], tl[4];
            LDMX4(th, bd);
            LDMX4(tl, bd + (SM_BL - SM_BH));
            // x4 reg order: [rows0-7@k0, rows8-15@k0, rows0-7@k+8, rows8-15@k+8]
            uint32_t bh0[2] = {th[0], th[2]}, bh1[2] = {th[1], th[3]};
            uint32_t bl0[2] = {tl[0], tl[2]}, bl1[2] = {tl[1], tl[3]};
#pragma unroll
            for (int mf = 0; mf < 2; mf++) {
                MMA16816(d[mf][2 * p], ah[mf], bh0);
                MMA16816(d[mf][2 * p], ah[mf], bl0);
                MMA16816(d[mf][2 * p], al[mf], bh0);
                MMA16816(d[mf][2 * p + 1], ah[mf], bh1);
                MMA16816(d[mf][2 * p + 1], ah[mf], bl1);
                MMA16816(d[mf][2 * p + 1], al[mf], bh1);
            }
        }
    }

    // epilogue: bias + direct float2 stores (fragment layout)
    int gq = lane >> 2, tig = lane & 3;
#pragma unroll
    for (int nf = 0; nf < 8; nf++) {
        int ncol = n0 + wc * 64 + nf * 8 + tig * 2;
        float2 bb = *(const float2*)&bfc[ncol];
#pragma unroll
        for (int mf = 0; mf < 2; mf++) {
            int r = m0 + wr * 32 + mf * 16 + gq;
            float2 o0 = {d[mf][nf][0] + bb.x, d[mf][nf][1] + bb.y};
            float2 o1 = {d[mf][nf][2] + bb.x, d[mf][nf][3] + bb.y};
            *(float2*)&logits[(size_t)r * Vn + ncol] = o0;
            *(float2*)&logits[(size_t)(r + 8) * Vn + ncol] = o1;
        }
    }
}

// ---------------- launch ----------------
extern "C" void kernel_launch(void* const* d_in, const int* in_sizes, int n_in,
                              void* d_out, int out_size) {
    const void* x = d_in[0];
    const float* hidden = (const float*)d_in[1];
    const float* etab = (const float*)d_in[2];
    const float* W_ih = (const float*)d_in[3];
    const float* W_hh = (const float*)d_in[4];
    const float* b_ih = (const float*)d_in[5];
    const float* b_hh = (const float*)d_in[6];
    const float* W1 = (const float*)d_in[7];
    const float* W2 = (const float*)d_in[8];
    const float* v = (const float*)d_in[9];
    const float* Wp = (const float*)d_in[10];
    const float* bp = (const float*)d_in[11];
    const float* Wfc = (const float*)d_in[12];
    const float* bfc = (const float*)d_in[13];

    float* out = (float*)d_out;
    float* out_logits = out;
    float* out_hidden = out + (size_t)Bn * Tn * Vn;
    float* out_weights = out_hidden + Bn * Hn;

    static int smem_set = 0;
    if (!smem_set) {
        cudaFuncSetAttribute(k_logits_mma, cudaFuncAttributeMaxDynamicSharedMemorySize, SM_TOT);
        smem_set = 1;
    }

    k_wconv<<<(Vn * Hn) / 4 / 256, 256>>>(Wfc);
    k_embed<<<Bn * Tn, 128>>>((const unsigned*)x, etab, W_ih, b_ih, b_hh);
    k_rnn<<<Bn, 128>>>(hidden, W_hh, out_hidden);
    k_qk<<<dim3(8, 32), 128>>>(W1, W2);
    k_feat<<<Bn * Tn, 128>>>(v);
    k_score<<<dim3(8, 8, Bn), 256>>>();
    k_softmax<<<Bn * Tn, 256>>>(out_weights);
    k_ctx<<<dim3(4, 16, Bn), 128>>>();
    k_proj<<<dim3(4, 32), 128>>>(Wp, bp);
    k_logits_mma<<<dim3(Vn / 128, (Bn * Tn) / 128), 256, SM_TOT>>>(bfc, out_logits);
}